// round 15
// baseline (speedup 1.0000x reference)
#include <cuda_runtime.h>
#include <cuda_bf16.h>

#define MODIFIER_COL 11
#define OWNER_COL    24
#define MAXG         8192
#define F_DIM        128
#define WAITER_BLOCKS  8
#define WAITER_THREADS (WAITER_BLOCKS * 256)

// One 16B slot per graph: {count, s0, s1, marker}. All contributions arrive
// via no-return relaxed v4 REDs on this single address; same-address L2
// serialization makes a snapshot with marker==count!=0 complete. No fences,
// no acquires, no atomic returns anywhere in the hot path.
// Zero-initialized at load; the waiter resets each slot after consuming it.
__device__ float4 g_state[MAXG];

__device__ __forceinline__ void red_add_v4_relaxed(float4* p, float4 d)
{
    asm volatile(
        "red.relaxed.gpu.global.add.v4.f32 [%0], {%1,%2,%3,%4};"
        :: "l"(p), "f"(d.x), "f"(d.y), "f"(d.z), "f"(d.w) : "memory");
}

__device__ __forceinline__ float4 ld_volatile_v4(const float4* p)
{
    float4 v;
    asm volatile("ld.volatile.global.v4.f32 {%0,%1,%2,%3}, [%4];"
                 : "=f"(v.x), "=f"(v.y), "=f"(v.z), "=f"(v.w)
                 : "l"(p) : "memory");
    return v;
}

// Single kernel. Blocks [0, WAITER_BLOCKS): waiters (resident from t=0, one
// thread per graph, MLP overlapped with the reduce). Remaining blocks: R2's
// sorted-key warp segreduce, one v4 RED per segment head.
__global__ __launch_bounds__(256) void fused_kernel(
    const float* __restrict__ nf,
    const int*   __restrict__ batch,
    const float* __restrict__ W1,   // [32,2] row-major
    const float* __restrict__ b1,   // [32]
    const float* __restrict__ W2,   // [1,32]
    const float* __restrict__ b2,   // [1]
    float* __restrict__ out,
    int N, int G)
{
    if (blockIdx.x < WAITER_BLOCKS) {
        // ------------------------------ waiter ------------------------------
        const int wtid = blockIdx.x * blockDim.x + threadIdx.x;
        for (int g = wtid; g < G && g < MAXG; g += WAITER_THREADS) {
            float4 s;
            while (true) {
                s = ld_volatile_v4(&g_state[g]);
                if (s.w == s.x && s.w != 0.f) break;   // complete (or empty-poke)
                __nanosleep(100);
            }
            g_state[g] = make_float4(0.f, 0.f, 0.f, 0.f);  // reset for replay

            float cc = s.x;
            if (cc > 0.f) {
                float denom = cc;                       // cc >= 1 here
                float f0 = 1.f - s.y / denom;
                float f1 = 1.f - s.z / denom;
                float acc = __ldg(b2);
                #pragma unroll
                for (int j = 0; j < 32; ++j) {
                    float h = fmaf(f0, __ldg(W1 + 2 * j),
                              fmaf(f1, __ldg(W1 + 2 * j + 1), __ldg(b1 + j)));
                    h   = fmaxf(h, 0.f);
                    acc = fmaf(__ldg(W2 + j), h, acc);
                }
                out[g] = 1.f / (1.f + __expf(-acc));
            } else {
                out[g] = 0.f;                           // empty graph
            }
        }
        return;
    }

    // ------------------------------ reduce ------------------------------
    const int i    = (blockIdx.x - WAITER_BLOCKS) * blockDim.x + threadIdx.x;
    const int lane = threadIdx.x & 31;
    const bool valid = (i < N);

    int   g  = -1;
    float c  = 0.f, v0 = 0.f, v1 = 0.f;
    if (valid) {
        g  = batch[i];
        const float* row = nf + (size_t)i * F_DIM;
        v0 = __ldcs(row + MODIFIER_COL);
        v1 = __ldcs(row + OWNER_COL);
        c  = 1.f;
    }

    // Key of element i+1 (-1 = none): for end/gap detection.
    int gnext = __shfl_down_sync(0xffffffffu, g, 1);
    if (lane == 31) gnext = (valid && i + 1 < N) ? __ldg(batch + i + 1) : -1;
    if (valid && i == N - 1) gnext = -1;

    // Down-sweep segmented reduction (keys non-decreasing across lanes):
    // head lane ends with the sum over its run [lane, lane+run-1].
    #pragma unroll
    for (int d = 1; d < 32; d <<= 1) {
        int   go = __shfl_down_sync(0xffffffffu, g,  d);
        float co = __shfl_down_sync(0xffffffffu, c,  d);
        float a0 = __shfl_down_sync(0xffffffffu, v0, d);
        float a1 = __shfl_down_sync(0xffffffffu, v1, d);
        if (lane + d < 32 && go == g) { c += co; v0 += a0; v1 += a1; }
    }

    int  gprev = __shfl_up_sync(0xffffffffu, g, 1);
    bool head  = valid && (lane == 0 || gprev != g);

    // Key right after this head's run (run = (int)c, exact small int).
    int run = (int)c;
    int r   = min(max(lane + run - 1, 0), 31);
    int g_after = __shfl_sync(0xffffffffu, gnext, r);

    if (head && g >= 0 && g < MAXG) {
        // A head at lane>0 exists precisely because batch[i-1] != g, so it is
        // the graph's global start; lane 0 checks the global predecessor.
        bool is_start = (lane > 0) ? true
                        : (i == 0 || __ldg(batch + i - 1) != g);
        bool is_end   = (g_after != g);        // covers i_last == N-1

        float marker = (is_start ? -(float)i : 0.f)
                     + (is_end   ?  (float)(i + run) : 0.f);

        red_add_v4_relaxed(&g_state[g], make_float4(c, v0, v1, marker));

        // Empty-graph pokes (gaps in the sorted key sequence).
        if (is_end) {
            int hiG = (g_after < 0) ? G : g_after;
            for (int h = g + 1; h < hiG && h < MAXG; ++h)
                red_add_v4_relaxed(&g_state[h], make_float4(-1.f, 0.f, 0.f, -1.f));
        }
        if (is_start && i == 0) {
            for (int h = 0; h < g; ++h)
                red_add_v4_relaxed(&g_state[h], make_float4(-1.f, 0.f, 0.f, -1.f));
        }
    }
}

extern "C" void kernel_launch(void* const* d_in, const int* in_sizes, int n_in,
                              void* d_out, int out_size)
{
    // order: node_features, batch, graph_embedding, W1, b1, W2, b2
    const float* nf    = (const float*)d_in[0];
    const int*   batch = (const int*)d_in[1];
    const float* W1    = (const float*)d_in[3];
    const float* b1    = (const float*)d_in[4];
    const float* W2    = (const float*)d_in[5];
    const float* b2    = (const float*)d_in[6];
    float*       out   = (float*)d_out;

    int N = in_sizes[1];
    int G = in_sizes[2] / F_DIM;
    if (G <= 0 || G > MAXG) G = out_size;

    int rb = (N + 255) / 256;
    fused_kernel<<<WAITER_BLOCKS + rb, 256>>>(nf, batch, W1, b1, W2, b2, out, N, G);
}